// round 1
// baseline (speedup 1.0000x reference)
#include <cuda_runtime.h>
#include <cuda_bf16.h>

#define DIM    1024
#define HIDDEN 4096
#define NNZ    262144
#define TOK    512

// ---------------- scratch (__device__ globals; no allocations) ----------------
__device__ float g_xT[DIM * TOK];        // [c][t]
__device__ float g_hiddenT[HIDDEN * TOK];// [h][t]
__device__ float g_downT[DIM * TOK];     // [d][t]

__device__ int   g_cnt_up[HIDDEN],   g_cnt_gate[HIDDEN],   g_cnt_down[DIM];
__device__ int   g_ptr_up[HIDDEN+1], g_ptr_gate[HIDDEN+1], g_ptr_down[DIM+1];
__device__ int   g_cur_up[HIDDEN],   g_cur_gate[HIDDEN],   g_cur_down[DIM];

__device__ int   g_col_up[NNZ];   __device__ float g_val_up[NNZ];
__device__ int   g_col_gate[NNZ]; __device__ float g_val_gate[NNZ];
__device__ int   g_col_down[NNZ]; __device__ float g_val_down[NNZ];

// ---------------- phase 0: counting sort by row ----------------
__global__ void zero_counts() {
    int i = blockIdx.x * blockDim.x + threadIdx.x;
    if (i < HIDDEN) { g_cnt_up[i] = 0; g_cnt_gate[i] = 0; }
    if (i < DIM)    { g_cnt_down[i] = 0; }
}

__global__ void hist_rows(const int* __restrict__ up_row,
                          const int* __restrict__ gate_row,
                          const int* __restrict__ down_row) {
    int i = blockIdx.x * blockDim.x + threadIdx.x;
    if (i < NNZ)            atomicAdd(&g_cnt_up[up_row[i]], 1);
    else if (i < 2*NNZ)     atomicAdd(&g_cnt_gate[gate_row[i - NNZ]], 1);
    else if (i < 3*NNZ)     atomicAdd(&g_cnt_down[down_row[i - 2*NNZ]], 1);
}

// One block of 1024 threads; exclusive scan of an array of n (n/1024 elems per thread).
template<int PER>
__device__ void scan_array(const int* cnt, int* ptr, int* cur, int n) {
    __shared__ int sh[1024];
    int tid = threadIdx.x;
    int base = tid * PER;
    int local[PER];
    int s = 0;
#pragma unroll
    for (int i = 0; i < PER; i++) { local[i] = s; s += cnt[base + i]; }
    sh[tid] = s;
    __syncthreads();
    // Hillis-Steele inclusive scan over 1024 partials
#pragma unroll
    for (int off = 1; off < 1024; off <<= 1) {
        int add = (tid >= off) ? sh[tid - off] : 0;
        __syncthreads();
        sh[tid] += add;
        __syncthreads();
    }
    int excl = (tid > 0) ? sh[tid - 1] : 0;
#pragma unroll
    for (int i = 0; i < PER; i++) {
        int p = excl + local[i];
        ptr[base + i] = p;
        cur[base + i] = p;
    }
    if (tid == 1023) ptr[n] = sh[1023];
    __syncthreads();
}

__global__ void scan_counts() {
    scan_array<4>(g_cnt_up,   g_ptr_up,   g_cur_up,   HIDDEN);
    scan_array<4>(g_cnt_gate, g_ptr_gate, g_cur_gate, HIDDEN);
    scan_array<1>(g_cnt_down, g_ptr_down, g_cur_down, DIM);
}

__global__ void scatter_sorted(const int* __restrict__ up_row,   const int* __restrict__ up_col,   const float* __restrict__ up_val,
                               const int* __restrict__ gate_row, const int* __restrict__ gate_col, const float* __restrict__ gate_val,
                               const int* __restrict__ down_row, const int* __restrict__ down_col, const float* __restrict__ down_val) {
    int i = blockIdx.x * blockDim.x + threadIdx.x;
    if (i < NNZ) {
        int r = up_row[i];
        int pos = atomicAdd(&g_cur_up[r], 1);
        g_col_up[pos] = up_col[i];
        g_val_up[pos] = up_val[i];
    } else if (i < 2*NNZ) {
        int j = i - NNZ;
        int r = gate_row[j];
        int pos = atomicAdd(&g_cur_gate[r], 1);
        g_col_gate[pos] = gate_col[j];
        g_val_gate[pos] = gate_val[j];
    } else if (i < 3*NNZ) {
        int j = i - 2*NNZ;
        int r = down_row[j];
        int pos = atomicAdd(&g_cur_down[r], 1);
        g_col_down[pos] = down_col[j];
        g_val_down[pos] = down_val[j];
    }
}

// ---------------- phase 1: transpose x [T, DIM] -> xT [DIM, T] ----------------
__global__ void transpose_x(const float* __restrict__ x) {
    __shared__ float sh[32][33];
    int c0 = blockIdx.x * 32, t0 = blockIdx.y * 32;
    int tx = threadIdx.x, ty = threadIdx.y;
    sh[ty][tx] = x[(t0 + ty) * DIM + (c0 + tx)];   // coalesced read
    __syncthreads();
    g_xT[(c0 + ty) * TOK + (t0 + tx)] = sh[tx][ty]; // coalesced write
}

// ---------------- phase 2: fused up/gate + SiLU ----------------
__global__ void __launch_bounds__(TOK) upgate_kernel(const float* __restrict__ up_bias,
                                                     const float* __restrict__ gate_bias) {
    int r = blockIdx.x;
    int t = threadIdx.x;

    float au = 0.f;
    {
        int s = g_ptr_up[r], e = g_ptr_up[r + 1];
#pragma unroll 4
        for (int i = s; i < e; i++) {
            int   c = g_col_up[i];
            float v = g_val_up[i];
            au += v * g_xT[c * TOK + t];
        }
    }
    float ag = 0.f;
    {
        int s = g_ptr_gate[r], e = g_ptr_gate[r + 1];
#pragma unroll 4
        for (int i = s; i < e; i++) {
            int   c = g_col_gate[i];
            float v = g_val_gate[i];
            ag += v * g_xT[c * TOK + t];
        }
    }
    float u = au + up_bias[r];
    float g = ag + gate_bias[r];
    float h = (u / (1.f + __expf(-u))) * g;   // silu(u) * g
    g_hiddenT[r * TOK + t] = h;
}

// ---------------- phase 3: down projection ----------------
__global__ void __launch_bounds__(TOK) down_kernel(const float* __restrict__ down_bias) {
    int r = blockIdx.x;
    int t = threadIdx.x;
    float acc = 0.f;
    int s = g_ptr_down[r], e = g_ptr_down[r + 1];
#pragma unroll 4
    for (int i = s; i < e; i++) {
        int   c = g_col_down[i];
        float v = g_val_down[i];
        acc += v * g_hiddenT[c * TOK + t];
    }
    g_downT[r * TOK + t] = acc + down_bias[r];
}

// ---------------- phase 4: out[t,d] = x[t,d] + downT[d,t] ----------------
__global__ void final_kernel(const float* __restrict__ x, float* __restrict__ out) {
    __shared__ float sh[32][33];
    int d0 = blockIdx.x * 32, t0 = blockIdx.y * 32;
    int tx = threadIdx.x, ty = threadIdx.y;
    sh[ty][tx] = g_downT[(d0 + ty) * TOK + (t0 + tx)]; // coalesced read of downT
    __syncthreads();
    int t = t0 + ty, d = d0 + tx;
    out[t * DIM + d] = x[t * DIM + d] + sh[tx][ty];    // coalesced write
}

// ---------------- launcher ----------------
extern "C" void kernel_launch(void* const* d_in, const int* in_sizes, int n_in,
                              void* d_out, int out_size) {
    const float* x         = (const float*)d_in[0];
    const int*   up_row    = (const int*)  d_in[1];
    const int*   up_col    = (const int*)  d_in[2];
    const float* up_val    = (const float*)d_in[3];
    const float* up_bias   = (const float*)d_in[4];
    const int*   gate_row  = (const int*)  d_in[5];
    const int*   gate_col  = (const int*)  d_in[6];
    const float* gate_val  = (const float*)d_in[7];
    const float* gate_bias = (const float*)d_in[8];
    const int*   down_row  = (const int*)  d_in[9];
    const int*   down_col  = (const int*)  d_in[10];
    const float* down_val  = (const float*)d_in[11];
    const float* down_bias = (const float*)d_in[12];
    float* out = (float*)d_out;

    // phase 0: sort COO by row
    zero_counts<<<(HIDDEN + 255) / 256, 256>>>();
    hist_rows<<<(3 * NNZ + 255) / 256, 256>>>(up_row, gate_row, down_row);
    scan_counts<<<1, 1024>>>();
    scatter_sorted<<<(3 * NNZ + 255) / 256, 256>>>(up_row, up_col, up_val,
                                                   gate_row, gate_col, gate_val,
                                                   down_row, down_col, down_val);
    // phase 1: transpose activations
    transpose_x<<<dim3(DIM / 32, TOK / 32), dim3(32, 32)>>>(x);
    // phase 2: up/gate + SiLU
    upgate_kernel<<<HIDDEN, TOK>>>(up_bias, gate_bias);
    // phase 3: down
    down_kernel<<<DIM, TOK>>>(down_bias);
    // phase 4: residual add + transpose to output layout
    final_kernel<<<dim3(DIM / 32, TOK / 32), dim3(32, 32)>>>(x, out);
}